// round 3
// baseline (speedup 1.0000x reference)
#include <cuda_runtime.h>
#include <cstdint>
#include <cstddef>
#include <math.h>

// Problem dims (fixed by the reference)
#define SS   128      // seq len
#define BBT  128      // batch
#define EE   256      // embed
#define HHD  256      // hidden
#define G4   1024     // 4*H
#define NSEQ 3
#define NSTREAM 768   // 3 seqs * 2 dirs * 128 batch rows
#define D2H  512      // 2*H

// persistent-LSTM tiling
#define RPB 48        // stream rows per cluster (16 clusters * 48 = 768)
#define UPB 32        // hidden units per CTA (8 CTAs * 32 = 256)
#define WT_PITCH 132  // smem pitch for W slice [256][132]
#define HS_PITCH 260  // smem pitch for h tile  [48][260]
#define GT_PITCH 132  // smem pitch for gate tile [48][132] (aliases Hs)
#define SMEM_PERSIST ((256 * WT_PITCH + RPB * HS_PITCH) * 4)   // 185088 B

// ---------------- scratch (device globals; no cudaMalloc allowed) ------------
__device__ float g_Gf  [(size_t)NSEQ*SS*BBT*G4];        // 201 MB  [seq][s][b][4H]
__device__ float g_Gb  [(size_t)NSEQ*SS*BBT*G4];        // 201 MB
__device__ float g_out [(size_t)NSEQ*BBT*SS*D2H];       // 101 MB  [seq][b][s][2H]
__device__ float g_h   [2*NSTREAM*HHD];                 // double-buffered h state
__device__ float g_c   [NSTREAM*HHD];                   // cell state (init only)
__device__ float g_Ct  [(size_t)BBT*SS*D2H];            // tanh(S1(C0))
__device__ float g_Hm  [(size_t)BBT*SS*SS];
__device__ float g_AQ  [(size_t)BBT*SS*SS];
__device__ float g_AC  [(size_t)BBT*SS*SS];

__device__ __forceinline__ float sigf(float x) { return 1.0f / (1.0f + expf(-x)); }

// ---- packed fp32x2 helpers (scalar FFMA is half-rate on Blackwell) ----------
__device__ __forceinline__ unsigned long long pk2(float lo, float hi) {
    unsigned long long r;
    asm("mov.b64 %0,{%1,%2};" : "=l"(r) : "f"(lo), "f"(hi));
    return r;
}
__device__ __forceinline__ unsigned long long ffma2(unsigned long long a,
                                                    unsigned long long b,
                                                    unsigned long long c) {
    unsigned long long d;
    asm("fma.rn.f32x2 %0,%1,%2,%3;" : "=l"(d) : "l"(a), "l"(b), "l"(c));
    return d;
}
__device__ __forceinline__ float2 upk2(unsigned long long v) {
    float2 r;
    asm("mov.b64 {%0,%1},%2;" : "=f"(r.x), "=f"(r.y) : "l"(v));
    return r;
}

// ---------------- init states from input hidden/cell -------------------------
__global__ void init_state(const float* hQ, const float* cQ, const float* hC, const float* cC,
                           const float* hC2, const float* cC2) {
    int i = blockIdx.x * 256 + threadIdx.x;             // 768*256
    if (i >= NSTREAM * HHD) return;
    int m = i >> 8, k = i & 255;
    int half = m / 384;                                 // 0 fwd, 1 bwd
    int mm = m % 384;
    int seq = mm >> 7, bb = mm & 127;
    const float* hsrc = (seq == 0) ? hQ : (seq == 1) ? hC : hC2;
    const float* csrc = (seq == 0) ? cQ : (seq == 1) ? cC : cC2;
    g_h[i] = hsrc[(half * BBT + bb) * HHD + k];         // into buffer 0
    g_c[i] = csrc[(half * BBT + bb) * HHD + k];
}

// ---------------- fused embed-gather + input projection ----------------------
// G[row][:] = emb[tok(row)] @ W^T + b1 + b2.  Rows: seq*16384 + s*128 + b.
// Tile 128x128, BK=16, 256 threads, 8x8 per thread (f32x2 packed FMA).
__global__ void __launch_bounds__(256) gemm_inproj(
    const int* __restrict__ iQ, const int* __restrict__ iC, const int* __restrict__ iC2,
    const float* __restrict__ emb,
    const float* __restrict__ W, const float* __restrict__ b1, const float* __restrict__ b2,
    float* __restrict__ G) {
    int m0 = blockIdx.y * 128, n0 = blockIdx.x * 128;
    __shared__ float As[16][136];
    __shared__ float Ws[16][136];
    __shared__ int   toks[128];
    int tid = threadIdx.x;
    if (tid < 128) {
        int row = m0 + tid;
        int seq = row >> 14, rem = row & 16383;
        const int* idx = (seq == 0) ? iQ : (seq == 1) ? iC : iC2;
        toks[tid] = idx[rem];
    }
    __syncthreads();
    int tx = tid & 15, ty = tid >> 4;
    unsigned long long acc[8][4];
#pragma unroll
    for (int i = 0; i < 8; i++)
#pragma unroll
        for (int j = 0; j < 4; j++) acc[i][j] = 0ull;
    for (int k0 = 0; k0 < EE; k0 += 16) {
#pragma unroll
        for (int i = 0; i < 2; i++) {                   // A tile: 512 float4
            int q = i * 256 + tid;
            int r = q >> 2, kq = q & 3;
            float4 v = *(const float4*)&emb[(size_t)toks[r] * EE + k0 + kq * 4];
            As[kq * 4 + 0][r] = v.x; As[kq * 4 + 1][r] = v.y;
            As[kq * 4 + 2][r] = v.z; As[kq * 4 + 3][r] = v.w;
        }
#pragma unroll
        for (int i = 0; i < 2; i++) {                   // W tile: 512 float4
            int q = i * 256 + tid;
            int r = q >> 2, kq = q & 3;
            float4 v = *(const float4*)&W[(size_t)(n0 + r) * EE + k0 + kq * 4];
            Ws[kq * 4 + 0][r] = v.x; Ws[kq * 4 + 1][r] = v.y;
            Ws[kq * 4 + 2][r] = v.z; Ws[kq * 4 + 3][r] = v.w;
        }
        __syncthreads();
#pragma unroll
        for (int kk = 0; kk < 16; kk++) {
            float4 a0 = *(const float4*)&As[kk][ty * 8];
            float4 a1 = *(const float4*)&As[kk][ty * 8 + 4];
            ulonglong2 w0 = *(const ulonglong2*)&Ws[kk][tx * 8];
            ulonglong2 w1 = *(const ulonglong2*)&Ws[kk][tx * 8 + 4];
            float av[8] = {a0.x, a0.y, a0.z, a0.w, a1.x, a1.y, a1.z, a1.w};
#pragma unroll
            for (int i = 0; i < 8; i++) {
                unsigned long long ap = pk2(av[i], av[i]);
                acc[i][0] = ffma2(ap, w0.x, acc[i][0]);
                acc[i][1] = ffma2(ap, w0.y, acc[i][1]);
                acc[i][2] = ffma2(ap, w1.x, acc[i][2]);
                acc[i][3] = ffma2(ap, w1.y, acc[i][3]);
            }
        }
        __syncthreads();
    }
    int colb = n0 + tx * 8;
    float bv[8];
#pragma unroll
    for (int j = 0; j < 8; j++) bv[j] = b1[colb + j] + b2[colb + j];
#pragma unroll
    for (int i = 0; i < 8; i++) {
        float* dst = &G[(size_t)(m0 + ty * 8 + i) * G4 + colb];
        float2 p0 = upk2(acc[i][0]), p1 = upk2(acc[i][1]);
        float2 p2 = upk2(acc[i][2]), p3 = upk2(acc[i][3]);
        float4 o0 = {p0.x + bv[0], p0.y + bv[1], p1.x + bv[2], p1.y + bv[3]};
        float4 o1 = {p2.x + bv[4], p2.y + bv[5], p3.x + bv[6], p3.y + bv[7]};
        *(float4*)dst = o0; *(float4*)(dst + 4) = o1;
    }
}

// ---------------- generic GEMM: C = act(A @ W^T + b1), batched over z --------
// A: [M,K] rm, W: [N,K] rm, C: [M,N] rm. 128x128 tile, BK=16, 256 thr, 8x8/thr.
template <int ACT>
__global__ void __launch_bounds__(256) gemm_atb(
    const float* __restrict__ Ag, size_t sA,
    const float* __restrict__ Wg, size_t sW,
    const float* __restrict__ b1,
    float* __restrict__ Cg, size_t sC, int N, int K) {
    const float* A = Ag + (size_t)blockIdx.z * sA;
    const float* W = Wg + (size_t)blockIdx.z * sW;
    float*       C = Cg + (size_t)blockIdx.z * sC;
    int m0 = blockIdx.y * 128, n0 = blockIdx.x * 128;
    __shared__ float As[16][136];
    __shared__ float Ws[16][136];
    int tid = threadIdx.x;
    int tx = tid & 15, ty = tid >> 4;
    unsigned long long acc[8][4];
#pragma unroll
    for (int i = 0; i < 8; i++)
#pragma unroll
        for (int j = 0; j < 4; j++) acc[i][j] = 0ull;
    for (int k0 = 0; k0 < K; k0 += 16) {
#pragma unroll
        for (int i = 0; i < 2; i++) {
            int q = i * 256 + tid;
            int r = q >> 2, kq = q & 3;
            float4 v = *(const float4*)&A[(size_t)(m0 + r) * K + k0 + kq * 4];
            As[kq * 4 + 0][r] = v.x; As[kq * 4 + 1][r] = v.y;
            As[kq * 4 + 2][r] = v.z; As[kq * 4 + 3][r] = v.w;
        }
#pragma unroll
        for (int i = 0; i < 2; i++) {
            int q = i * 256 + tid;
            int r = q >> 2, kq = q & 3;
            float4 v = *(const float4*)&W[(size_t)(n0 + r) * K + k0 + kq * 4];
            Ws[kq * 4 + 0][r] = v.x; Ws[kq * 4 + 1][r] = v.y;
            Ws[kq * 4 + 2][r] = v.z; Ws[kq * 4 + 3][r] = v.w;
        }
        __syncthreads();
#pragma unroll
        for (int kk = 0; kk < 16; kk++) {
            float4 a0 = *(const float4*)&As[kk][ty * 8];
            float4 a1 = *(const float4*)&As[kk][ty * 8 + 4];
            ulonglong2 w0 = *(const ulonglong2*)&Ws[kk][tx * 8];
            ulonglong2 w1 = *(const ulonglong2*)&Ws[kk][tx * 8 + 4];
            float av[8] = {a0.x, a0.y, a0.z, a0.w, a1.x, a1.y, a1.z, a1.w};
#pragma unroll
            for (int i = 0; i < 8; i++) {
                unsigned long long ap = pk2(av[i], av[i]);
                acc[i][0] = ffma2(ap, w0.x, acc[i][0]);
                acc[i][1] = ffma2(ap, w0.y, acc[i][1]);
                acc[i][2] = ffma2(ap, w1.x, acc[i][2]);
                acc[i][3] = ffma2(ap, w1.y, acc[i][3]);
            }
        }
        __syncthreads();
    }
    int colb = n0 + tx * 8;
    float bv[8];
#pragma unroll
    for (int j = 0; j < 8; j++) bv[j] = b1 ? b1[colb + j] : 0.f;
#pragma unroll
    for (int i = 0; i < 8; i++) {
        float* dst = &C[(size_t)(m0 + ty * 8 + i) * N + colb];
        float2 p[4] = {upk2(acc[i][0]), upk2(acc[i][1]), upk2(acc[i][2]), upk2(acc[i][3])};
        float o[8] = {p[0].x, p[0].y, p[1].x, p[1].y, p[2].x, p[2].y, p[3].x, p[3].y};
#pragma unroll
        for (int j = 0; j < 8; j++) {
            o[j] += bv[j];
            if (ACT == 1) o[j] = tanhf(o[j]);
        }
        float4 o0 = {o[0], o[1], o[2], o[3]}, o1 = {o[4], o[5], o[6], o[7]};
        *(float4*)dst = o0; *(float4*)(dst + 4) = o1;
    }
}

// ---------------- generic GEMM: C = A @ B, batched over z --------------------
// A: [M,K] rm, B: [K,N] rm. BM=64, BN=64, BK=16, 256 thr, 4x4/thr.
__global__ void __launch_bounds__(256) gemm_ab(
    const float* __restrict__ Ag, size_t sA,
    const float* __restrict__ Bg, size_t sB,
    float* __restrict__ Cg, size_t sC, int N, int K) {
    const float* A = Ag + (size_t)blockIdx.z * sA;
    const float* B = Bg + (size_t)blockIdx.z * sB;
    float*       C = Cg + (size_t)blockIdx.z * sC;
    int m0 = blockIdx.y * 64, n0 = blockIdx.x * 64;
    __shared__ float As[16][68];
    __shared__ float Bs[16][68];
    int tid = threadIdx.x;
    int tx = tid & 15, ty = tid >> 4;
    float acc[4][4] = {};
    for (int k0 = 0; k0 < K; k0 += 16) {
        {   // A: 256 float4, transpose into As
            int r = tid >> 2, kq = tid & 3;
            float4 v = *(const float4*)&A[(size_t)(m0 + r) * K + k0 + kq * 4];
            As[kq * 4 + 0][r] = v.x; As[kq * 4 + 1][r] = v.y;
            As[kq * 4 + 2][r] = v.z; As[kq * 4 + 3][r] = v.w;
        }
        {   // B: 256 float4, direct
            int kr = tid >> 4, nq = tid & 15;
            float4 v = *(const float4*)&B[(size_t)(k0 + kr) * N + n0 + nq * 4];
            Bs[kr][nq * 4 + 0] = v.x; Bs[kr][nq * 4 + 1] = v.y;
            Bs[kr][nq * 4 + 2] = v.z; Bs[kr][nq * 4 + 3] = v.w;
        }
        __syncthreads();
#pragma unroll
        for (int kk = 0; kk < 16; kk++) {
            float a[4], b[4];
#pragma unroll
            for (int i = 0; i < 4; i++) a[i] = As[kk][ty * 4 + i];
#pragma unroll
            for (int j = 0; j < 4; j++) b[j] = Bs[kk][tx * 4 + j];
#pragma unroll
            for (int i = 0; i < 4; i++)
#pragma unroll
                for (int j = 0; j < 4; j++) acc[i][j] += a[i] * b[j];
        }
        __syncthreads();
    }
#pragma unroll
    for (int i = 0; i < 4; i++) {
        float4 o; o.x = acc[i][0]; o.y = acc[i][1]; o.z = acc[i][2]; o.w = acc[i][3];
        *(float4*)&C[(size_t)(m0 + ty * 4 + i) * N + n0 + tx * 4] = o;
    }
}

// ---------------- persistent recurrence kernel -------------------------------
// grid (8,16), 256 threads, cluster (8,1,1): each cluster = one 48-row block;
// each CTA owns 32 hidden units (128 gate cols) with its Whh slice in smem for
// all 128 steps. Cell state in registers. h exchanged intra-cluster via .cg
// global + threadfence + barrier.cluster per step.
__global__ void __launch_bounds__(256, 1) __cluster_dims__(8, 1, 1)
lstm_persistent(const float* __restrict__ Whh_f, const float* __restrict__ Whh_b) {
    extern __shared__ float sm[];
    float* Wt = sm;                        // [256][WT_PITCH]
    float* Hs = sm + 256 * WT_PITCH;       // [48][HS_PITCH]; aliased as Gt [48][GT_PITCH]
    float* Gt = Hs;

    int tid = threadIdx.x;
    int ub = blockIdx.x;                   // 0..7  unit block
    int rb = blockIdx.y;                   // 0..15 row block
    int m0 = rb * RPB;
    int u0 = ub * UPB;
    bool bwd = (rb >= 8);
    const float* W  = bwd ? Whh_b : Whh_f;
    const float* Gx = bwd ? g_Gb : g_Gf;

    // load Whh slice transposed: Wt[k][c] = W[gate(c)*256 + u0 + (c&31)][k]
    {
        int c = tid >> 1, kh = tid & 1;
        int gc = ((c >> 5) << 8) + u0 + (c & 31);
        const float* wr = W + (size_t)gc * HHD + kh * 128;
#pragma unroll 4
        for (int j = 0; j < 128; j += 4) {
            float4 v = *(const float4*)&wr[j];
            int k = kh * 128 + j;
            Wt[(k + 0) * WT_PITCH + c] = v.x;
            Wt[(k + 1) * WT_PITCH + c] = v.y;
            Wt[(k + 2) * WT_PITCH + c] = v.z;
            Wt[(k + 3) * WT_PITCH + c] = v.w;
        }
    }

    // cell state in registers: 6 (row,unit) pairs per thread
    float creg[6];
#pragma unroll
    for (int q = 0; q < 6; q++) {
        int p = tid + q * 256;
        int r = p >> 5, uo = p & 31;
        creg[q] = g_c[((size_t)(m0 + r) << 8) + u0 + uo];
    }

    int tx = tid & 15, ty = tid >> 4;      // cols 8*tx, rows 3*ty
    const float* wb = Wt + 8 * tx;
    __syncthreads();

    for (int t = 0; t < SS; t++) {
        const float* hsrc = g_h + (size_t)(t & 1) * (NSTREAM * HHD);
        float*       hdst = g_h + (size_t)((t & 1) ^ 1) * (NSTREAM * HHD);

        // load h tile [48][256] into smem (L2-coherent .cg loads)
#pragma unroll
        for (int j = 0; j < 12; j++) {
            int lin = j * 256 + tid;       // float4 index over 48*64
            int row = lin >> 6, k4 = lin & 63;
            float4 v = __ldcg((const float4*)&hsrc[((size_t)(m0 + row) << 8) + k4 * 4]);
            *(float4*)&Hs[row * HS_PITCH + k4 * 4] = v;
        }
        __syncthreads();

        // GEMM: 3 rows x 8 cols per thread, K=256, packed f32x2
        unsigned long long acc[3][4];
#pragma unroll
        for (int i = 0; i < 3; i++)
#pragma unroll
            for (int j = 0; j < 4; j++) acc[i][j] = 0ull;
        const float* h0p = Hs + (3 * ty + 0) * HS_PITCH;
        const float* h1p = h0p + HS_PITCH;
        const float* h2p = h1p + HS_PITCH;
#pragma unroll 8
        for (int k = 0; k < HHD; k++) {
            unsigned long long ap0 = pk2(h0p[k], h0p[k]);
            unsigned long long ap1 = pk2(h1p[k], h1p[k]);
            unsigned long long ap2 = pk2(h2p[k], h2p[k]);
            ulonglong2 wA = *(const ulonglong2*)(wb + k * WT_PITCH);
            ulonglong2 wB = *(const ulonglong2*)(wb + k * WT_PITCH + 4);
            acc[0][0] = ffma2(ap0, wA.x, acc[0][0]);
            acc[0][1] = ffma2(ap0, wA.y, acc[0][1]);
            acc[0][2] = ffma2(ap0, wB.x, acc[0][2]);
            acc[0][3] = ffma2(ap0, wB.y, acc[0][3]);
            acc[1][0] = ffma2(ap1, wA.x, acc[1][0]);
            acc[1][1] = ffma2(ap1, wA.y, acc[1][1]);
            acc[1][2] = ffma2(ap1, wB.x, acc[1][2]);
            acc[1][3] = ffma2(ap1, wB.y, acc[1][3]);
            acc[2][0] = ffma2(ap2, wA.x, acc[2][0]);
            acc[2][1] = ffma2(ap2, wA.y, acc[2][1]);
            acc[2][2] = ffma2(ap2, wB.x, acc[2][2]);
            acc[2][3] = ffma2(ap2, wB.y, acc[2][3]);
        }
        __syncthreads();   // all reads of Hs done (Gt aliases it)

        // add hoisted input gates, stage to Gt
        int tq = bwd ? (SS - 1 - t) : t;
#pragma unroll
        for (int i = 0; i < 3; i++) {
            int mg = m0 + 3 * ty + i;
            int mm = bwd ? (mg - 384) : mg;
            int seq = mm >> 7, bb = mm & 127;
            size_t gbase = (((size_t)seq * SS + tq) * BBT + bb) * G4;
#pragma unroll
            for (int jp = 0; jp < 2; jp++) {
                int c0 = 8 * tx + 4 * jp;
                int gc = ((c0 >> 5) << 8) + u0 + (c0 & 31);
                float4 gx = *(const float4*)&Gx[gbase + gc];
                float2 p0 = upk2(acc[i][2 * jp]);
                float2 p1 = upk2(acc[i][2 * jp + 1]);
                float4 o = {gx.x + p0.x, gx.y + p0.y, gx.z + p1.x, gx.w + p1.y};
                *(float4*)&Gt[(3 * ty + i) * GT_PITCH + c0] = o;
            }
        }
        __syncthreads();

        // pointwise: gates -> c,h ; scatter h to g_h (next buf) and g_out
#pragma unroll
        for (int q = 0; q < 6; q++) {
            int p = tid + q * 256;
            int r = p >> 5, uo = p & 31;
            float gi = Gt[r * GT_PITCH + uo];
            float gf = Gt[r * GT_PITCH + 32 + uo];
            float gg = Gt[r * GT_PITCH + 64 + uo];
            float go = Gt[r * GT_PITCH + 96 + uo];
            float cn = sigf(gf) * creg[q] + sigf(gi) * tanhf(gg);
            float hn = sigf(go) * tanhf(cn);
            creg[q] = cn;
            int mg = m0 + r;
            __stcg(&hdst[((size_t)mg << 8) + u0 + uo], hn);
            int mm = bwd ? (mg - 384) : mg;
            int seq = mm >> 7, bb = mm & 127;
            int coff = (bwd ? HHD : 0) + u0 + uo;
            g_out[(((size_t)seq * BBT + bb) * SS + tq) * D2H + coff] = hn;
        }

        __threadfence();   // h stores visible at L2 before peers proceed
        asm volatile("barrier.cluster.arrive.aligned;" ::: "memory");
        asm volatile("barrier.cluster.wait.aligned;" ::: "memory");
    }
}

// ---------------- fused row+col softmax of Hm --------------------------------
__global__ void __launch_bounds__(256) attn_softmax(const float* __restrict__ Hm,
                                                    float* __restrict__ AQ,
                                                    float* __restrict__ AC) {
    int b = blockIdx.x;
    const float* H = Hm + (size_t)b * SS * SS;
    int tid = threadIdx.x;
    if (tid < 128) {
        const float* row = H + tid * SS;
        float mx = -1e30f;
#pragma unroll 8
        for (int j = 0; j < SS; j++) mx = fmaxf(mx, row[j]);
        float s = 0.f;
#pragma unroll 8
        for (int j = 0; j < SS; j++) s += expf(row[j] - mx);
        float inv = 1.f / s;
        float* out = AQ + (size_t)b * SS * SS + tid * SS;
#pragma unroll 8
        for (int j = 0; j < SS; j++) out[j] = expf(row[j] - mx) * inv;
    } else {
        int c = tid - 128;
        float mx = -1e30f;
#pragma unroll 8
        for (int j = 0; j < SS; j++) mx = fmaxf(mx, H[j * SS + c]);
        float s = 0.f;
#pragma unroll 8
        for (int j = 0; j < SS; j++) s += expf(H[j * SS + c] - mx);
        float inv = 1.f / s;
        float* out = AC + (size_t)b * SS * SS + c * SS;
#pragma unroll 8
        for (int j = 0; j < SS; j++) out[j] = expf(H[j * SS + c] - mx) * inv;
    }
}

// ---------------- launcher ---------------------------------------------------
extern "C" void kernel_launch(void* const* d_in, const int* in_sizes, int n_in,
                              void* d_out, int out_size) {
    (void)in_sizes; (void)out_size;
    int base = n_in - 20;   // skip batch_size if present
    const int*   iQ    = (const int*)d_in[base + 0];
    const int*   iC    = (const int*)d_in[base + 1];
    const int*   iC2   = (const int*)d_in[base + 2];
    const float* hQ    = (const float*)d_in[base + 3];
    const float* cQ    = (const float*)d_in[base + 4];
    const float* hC    = (const float*)d_in[base + 5];
    const float* cC    = (const float*)d_in[base + 6];
    const float* hC2   = (const float*)d_in[base + 7];
    const float* cC2   = (const float*)d_in[base + 8];
    const float* emb   = (const float*)d_in[base + 9];
    const float* Wih_f = (const float*)d_in[base + 10];
    const float* Whh_f = (const float*)d_in[base + 11];
    const float* bih_f = (const float*)d_in[base + 12];
    const float* bhh_f = (const float*)d_in[base + 13];
    const float* Wih_b = (const float*)d_in[base + 14];
    const float* Whh_b = (const float*)d_in[base + 15];
    const float* bih_b = (const float*)d_in[base + 16];
    const float* bhh_b = (const float*)d_in[base + 17];
    const float* S1_W  = (const float*)d_in[base + 18];
    const float* S1_b  = (const float*)d_in[base + 19];
    float* dout = (float*)d_out;

    float *pGf, *pGb, *pOut, *pCt, *pHm, *pAQ, *pAC;
    cudaGetSymbolAddress((void**)&pGf, g_Gf);
    cudaGetSymbolAddress((void**)&pGb, g_Gb);
    cudaGetSymbolAddress((void**)&pOut, g_out);
    cudaGetSymbolAddress((void**)&pCt, g_Ct);
    cudaGetSymbolAddress((void**)&pHm, g_Hm);
    cudaGetSymbolAddress((void**)&pAQ, g_AQ);
    cudaGetSymbolAddress((void**)&pAC, g_AC);

    static bool attr_done = false;
    if (!attr_done) {
        cudaFuncSetAttribute(lstm_persistent,
                             cudaFuncAttributeMaxDynamicSharedMemorySize, SMEM_PERSIST);
        attr_done = true;
    }

    // 1. fused embedding gather + input projections (both biases folded in)
    {
        dim3 grid(G4 / 128, (NSEQ * SS * BBT) / 128);
        gemm_inproj<<<grid, 256>>>(iQ, iC, iC2, emb, Wih_f, bih_f, bhh_f, pGf);
        gemm_inproj<<<grid, 256>>>(iQ, iC, iC2, emb, Wih_b, bih_b, bhh_b, pGb);
    }

    // 2. init states
    init_state<<<(NSTREAM * HHD + 255) / 256, 256>>>(hQ, cQ, hC, cC, hC2, cC2);

    // 3. recurrence: one persistent clustered kernel, all 128 steps
    lstm_persistent<<<dim3(8, 16), 256, SMEM_PERSIST>>>(Whh_f, Whh_b);

    // 4. two attention blocks; MQ/MC land directly in d_out
    const float* pQ = pOut;  // out_q = seq 0, [B][S][2H]
    for (int a = 0; a < 2; a++) {
        const float* C0 = pOut + (size_t)(a + 1) * BBT * SS * D2H;   // out_c / out_c2
        // Ct = tanh(C0 @ S1_W^T + S1_b)
        gemm_atb<1><<<dim3(D2H / 128, (BBT * SS) / 128), 256>>>(
            C0, 0, S1_W, 0, S1_b, pCt, 0, D2H, D2H);
        // Hm_b = Q_b @ Ct_b^T   (batched over z)
        gemm_atb<0><<<dim3(1, 1, BBT), 256>>>(
            pQ, (size_t)SS * D2H, pCt, (size_t)SS * D2H, nullptr,
            pHm, (size_t)SS * SS, SS, D2H);
        // AQ / AC
        attn_softmax<<<BBT, 256>>>(pHm, pAQ, pAC);
        // MQ = AQ @ Q  -> out section 2a ;  MC = AC @ MQ -> out section 2a+1
        float* oMQ = dout + (size_t)(2 * a)     * BBT * SS * D2H;
        float* oMC = dout + (size_t)(2 * a + 1) * BBT * SS * D2H;
        gemm_ab<<<dim3(D2H / 64, SS / 64, BBT), 256>>>(
            pAQ, (size_t)SS * SS, pQ, (size_t)SS * D2H, oMQ, (size_t)SS * D2H, D2H, SS);
        gemm_ab<<<dim3(D2H / 64, SS / 64, BBT), 256>>>(
            pAC, (size_t)SS * SS, oMQ, (size_t)SS * D2H, oMC, (size_t)SS * D2H, D2H, SS);
    }
}